// round 2
// baseline (speedup 1.0000x reference)
#include <cuda_runtime.h>
#include <math.h>

// Problem constants
#define B   256
#define T1  127          // T-1 timesteps
#define D   512
#define H   512
#define G   2048         // 4*H gates
#define NL  3
#define OUT_ENC ((size_t)B * T1 * D)   // offset of input_encoded in d_out

// Persistent-kernel config
#define GRID 128
#define NT   256

// ---------------------------------------------------------------------------
// Scratch (device globals: allocation-free rule)
// ---------------------------------------------------------------------------
__device__ float g_pre0[(size_t)T1 * B * G];   // precomputed x@W_ih0^T + biases, [t][b][j]
__device__ float g_h[NL][B * H];
__device__ float g_c[NL][B * H];
__device__ float g_gates[NL][B * G];
__device__ unsigned g_bar_count;
__device__ unsigned g_gen;

// ---------------------------------------------------------------------------
// Software grid barrier (all GRID blocks guaranteed co-resident: GRID<=148,
// 1 small CTA per SM)
// ---------------------------------------------------------------------------
__device__ __forceinline__ void grid_barrier() {
    __syncthreads();
    if (threadIdx.x == 0) {
        __threadfence();
        unsigned gen = *(volatile unsigned*)&g_gen;
        unsigned arrived = atomicAdd(&g_bar_count, 1u);
        if (arrived == GRID - 1) {
            g_bar_count = 0;
            __threadfence();
            *(volatile unsigned*)&g_gen = gen + 1;
        } else {
            while (*(volatile unsigned*)&g_gen == gen) {}
        }
        __threadfence();
    }
    __syncthreads();
}

// ---------------------------------------------------------------------------
// 64x64 output tile GEMM: acc[4][4] += A[row0:row0+64, 0:512] * W[col0:col0+64, 0:512]^T
// A row-major with stride lda, W row-major with stride ldw (weights are [2048,512]).
// 256 threads, 4x4 microtile each. K fixed at 512.
// ---------------------------------------------------------------------------
__device__ __forceinline__ void mm_tile(const float* __restrict__ A, int lda,
                                        const float* __restrict__ W, int ldw,
                                        int row0, int col0,
                                        float acc[4][4], float* sA, float* sB) {
    const int t  = threadIdx.x;
    const int lm = t >> 2;           // 0..63 (row within tile for loading)
    const int lk = (t & 3) << 2;     // 0,4,8,12 (k offset within 16-chunk)
    const int tx = t & 15;           // n position
    const int ty = t >> 4;           // m position
    const float* Arow = A + (size_t)(row0 + lm) * lda + lk;
    const float* Wrow = W + (size_t)(col0 + lm) * ldw + lk;

    for (int kc = 0; kc < 512; kc += 16) {
        float4 a = *(const float4*)(Arow + kc);
        float4 b = *(const float4*)(Wrow + kc);
        __syncthreads();
        sA[(lk + 0) * 64 + lm] = a.x;
        sA[(lk + 1) * 64 + lm] = a.y;
        sA[(lk + 2) * 64 + lm] = a.z;
        sA[(lk + 3) * 64 + lm] = a.w;
        sB[(lk + 0) * 64 + lm] = b.x;
        sB[(lk + 1) * 64 + lm] = b.y;
        sB[(lk + 2) * 64 + lm] = b.z;
        sB[(lk + 3) * 64 + lm] = b.w;
        __syncthreads();
#pragma unroll
        for (int kk = 0; kk < 16; kk++) {
            float4 av = *(const float4*)(sA + kk * 64 + ty * 4);
            float4 bv = *(const float4*)(sB + kk * 64 + tx * 4);
            float ar[4] = {av.x, av.y, av.z, av.w};
            float br[4] = {bv.x, bv.y, bv.z, bv.w};
#pragma unroll
            for (int i = 0; i < 4; i++)
#pragma unroll
                for (int j = 0; j < 4; j++)
                    acc[i][j] += ar[i] * br[j];
        }
    }
}

__device__ __forceinline__ float sigm(float x) { return 1.f / (1.f + expf(-x)); }

// Elementwise LSTM cell update for layer l at step t (grid-strided)
__device__ __forceinline__ void lstm_ew(int l, int t, float* __restrict__ out) {
    for (int idx = blockIdx.x * NT + threadIdx.x; idx < B * H; idx += GRID * NT) {
        int b = idx >> 9;
        int k = idx & 511;
        const float* gb = &g_gates[l][(size_t)b * G];
        float ig = sigm(gb[k]);
        float fg = sigm(gb[H + k]);
        float gg = tanhf(gb[2 * H + k]);
        float og = sigm(gb[3 * H + k]);
        float c  = fg * g_c[l][idx] + ig * gg;
        float h  = og * tanhf(c);
        g_c[l][idx] = c;
        g_h[l][idx] = h;
        if (l == NL - 1)
            out[OUT_ENC + (size_t)b * T1 * H + (size_t)t * H + k] = h;
    }
}

// ---------------------------------------------------------------------------
// Kernel 1: attention weights + input_weighted output.
// Key identity: the h0/c0 attention terms are constant across d, and softmax is
// shift-invariant => attn[b,d] = softmax_d( sum_t x[b,t,d]*attn_w[2H+t] ),
// identical for every timestep. input_weighted[b,t,d] = attn[b,d]*x[b,t,d].
// ---------------------------------------------------------------------------
__global__ void attn_kernel(const float* __restrict__ x, const float* __restrict__ aw,
                            float* __restrict__ out) {
    __shared__ float saw[T1];
    __shared__ float red[512];
    int b = blockIdx.x, d = threadIdx.x;
    if (d < T1) saw[d] = aw[2 * H + d];
    __syncthreads();
    const float* xb = x + (size_t)b * T1 * D;
    float acc = 0.f;
    for (int t = 0; t < T1; t++) acc += xb[(size_t)t * D + d] * saw[t];
    red[d] = acc;
    __syncthreads();
    for (int s = 256; s > 0; s >>= 1) {
        if (d < s) red[d] = fmaxf(red[d], red[d + s]);
        __syncthreads();
    }
    float mx = red[0];
    __syncthreads();
    float e = expf(acc - mx);
    red[d] = e;
    __syncthreads();
    for (int s = 256; s > 0; s >>= 1) {
        if (d < s) red[d] += red[d + s];
        __syncthreads();
    }
    float a = e / red[0];
    float* ob = out + (size_t)b * T1 * D;
    for (int t = 0; t < T1; t++) ob[(size_t)t * D + d] = a * xb[(size_t)t * D + d];
}

// ---------------------------------------------------------------------------
// Kernel 2: precompute pre0[t][b][:] = weighted[b,t,:] @ W_ih[0]^T + b_ih0 + b_hh0
// One big [32512 x 512] x [512 x 2048] GEMM, time-parallel.
// grid = (T1*4, 32); each block one 64x64 tile (64 b-rows, fixed t).
// ---------------------------------------------------------------------------
__global__ void __launch_bounds__(NT) pre_gemm_kernel(const float* __restrict__ weighted,
                                                      const float* __restrict__ wih,
                                                      const float* __restrict__ bih,
                                                      const float* __restrict__ bhh) {
    __shared__ float sA[16 * 64];
    __shared__ float sB[16 * 64];
    int tstep = blockIdx.x >> 2;
    int b0    = (blockIdx.x & 3) * 64;
    int col0  = blockIdx.y * 64;
    float acc[4][4] = {};
    // A row (b0+m): weighted + (b0+m)*T1*D + tstep*D
    mm_tile(weighted + (size_t)tstep * D, T1 * D, wih, 512, b0, col0, acc, sA, sB);
    int tx = threadIdx.x & 15, ty = threadIdx.x >> 4;
    size_t base = (size_t)tstep * B * G;
#pragma unroll
    for (int i = 0; i < 4; i++)
#pragma unroll
        for (int j = 0; j < 4; j++) {
            int bb = b0 + ty * 4 + i;
            int c  = col0 + tx * 4 + j;
            g_pre0[base + (size_t)bb * G + c] = acc[i][j] + bih[c] + bhh[c];
        }
}

// ---------------------------------------------------------------------------
// Kernel 3: persistent recurrent kernel. 128 blocks, software grid barriers.
// Per step:  phase1: gates[l] = h[l]@W_hh[l]^T (+pre0 / +biases)   [3 tiles/block]
//            ew(l=0) | gates1 += h0@W_ih1^T | ew(1) | gates2 += h1@W_ih2^T | ew(2)
// ---------------------------------------------------------------------------
__global__ void __launch_bounds__(NT, 1) lstm_kernel(const float* __restrict__ wih,
                                                     const float* __restrict__ whh,
                                                     const float* __restrict__ bih,
                                                     const float* __restrict__ bhh,
                                                     float* __restrict__ out) {
    __shared__ float sA[16 * 64];
    __shared__ float sB[16 * 64];

    // zero-init h, c
    for (int idx = blockIdx.x * NT + threadIdx.x; idx < NL * B * H; idx += GRID * NT) {
        ((float*)g_h)[idx] = 0.f;
        ((float*)g_c)[idx] = 0.f;
    }
    grid_barrier();

    const int tile = blockIdx.x;         // 0..127
    const int row0 = (tile >> 5) * 64;   // 4 row tiles over B=256
    const int col0 = (tile & 31) * 64;   // 32 col tiles over G=2048
    const int tx = threadIdx.x & 15, ty = threadIdx.x >> 4;

    for (int t = 0; t < T1; t++) {
        // ---- phase 1: recurrent W_hh GEMMs for all 3 layers ----
        for (int l = 0; l < NL; l++) {
            float acc[4][4] = {};
            mm_tile(g_h[l], H, whh + (size_t)l * G * H, H, row0, col0, acc, sA, sB);
            if (l == 0) {
                size_t pbase = (size_t)t * B * G;
#pragma unroll
                for (int i = 0; i < 4; i++)
#pragma unroll
                    for (int j = 0; j < 4; j++) {
                        int r = row0 + ty * 4 + i, c = col0 + tx * 4 + j;
                        g_gates[0][(size_t)r * G + c] = acc[i][j] + g_pre0[pbase + (size_t)r * G + c];
                    }
            } else {
#pragma unroll
                for (int i = 0; i < 4; i++)
#pragma unroll
                    for (int j = 0; j < 4; j++) {
                        int r = row0 + ty * 4 + i, c = col0 + tx * 4 + j;
                        g_gates[l][(size_t)r * G + c] = acc[i][j] + bih[l * G + c] + bhh[l * G + c];
                    }
            }
        }
        grid_barrier();

        // ---- layer 0 cell update ----
        lstm_ew(0, t, out);
        grid_barrier();

        // ---- gates1 += h0_new @ W_ih[1]^T ----
        {
            float acc[4][4] = {};
            mm_tile(g_h[0], H, wih + (size_t)1 * G * H, H, row0, col0, acc, sA, sB);
#pragma unroll
            for (int i = 0; i < 4; i++)
#pragma unroll
                for (int j = 0; j < 4; j++) {
                    int r = row0 + ty * 4 + i, c = col0 + tx * 4 + j;
                    g_gates[1][(size_t)r * G + c] += acc[i][j];
                }
        }
        grid_barrier();

        // ---- layer 1 cell update ----
        lstm_ew(1, t, out);
        grid_barrier();

        // ---- gates2 += h1_new @ W_ih[2]^T ----
        {
            float acc[4][4] = {};
            mm_tile(g_h[1], H, wih + (size_t)2 * G * H, H, row0, col0, acc, sA, sB);
#pragma unroll
            for (int i = 0; i < 4; i++)
#pragma unroll
                for (int j = 0; j < 4; j++) {
                    int r = row0 + ty * 4 + i, c = col0 + tx * 4 + j;
                    g_gates[2][(size_t)r * G + c] += acc[i][j];
                }
        }
        grid_barrier();

        // ---- layer 2 cell update + write input_encoded ----
        lstm_ew(2, t, out);
        grid_barrier();
    }
}

// ---------------------------------------------------------------------------
extern "C" void kernel_launch(void* const* d_in, const int* in_sizes, int n_in,
                              void* d_out, int out_size) {
    const float* x   = (const float*)d_in[0];  // [B, T1, D]
    const float* wih = (const float*)d_in[1];  // [3, 2048, 512]
    const float* whh = (const float*)d_in[2];  // [3, 2048, 512]
    const float* bih = (const float*)d_in[3];  // [3, 2048]
    const float* bhh = (const float*)d_in[4];  // [3, 2048]
    const float* aw  = (const float*)d_in[5];  // [2H + T1, 1]
    float* out = (float*)d_out;                // [B*T1*D weighted | B*T1*H encoded]

    // 1) attention weights (time-invariant) + input_weighted output
    attn_kernel<<<B, 512>>>(x, aw, out);

    // 2) precompute layer-0 input gates for all timesteps
    dim3 pgrid(T1 * 4, G / 64);
    pre_gemm_kernel<<<pgrid, NT>>>(out, wih, bih, bhh);

    // 3) persistent recurrent kernel
    lstm_kernel<<<GRID, NT>>>(wih, whh, bih, bhh, out);
}

// round 3
// speedup vs baseline: 1.6355x; 1.6355x over previous
#include <cuda_runtime.h>
#include <cuda_bf16.h>
#include <math.h>
#include <stdint.h>

// Problem constants
#define B   256
#define T1  127          // T-1 timesteps
#define D   512
#define H   512
#define G   2048         // 4*H gates
#define NL  3
#define OUT_ENC ((size_t)B * T1 * D)   // offset of input_encoded in d_out

// Persistent-kernel config
#define GRID 128
#define NT   256

// ---------------------------------------------------------------------------
// Scratch (device globals: allocation-free rule)
// ---------------------------------------------------------------------------
__device__ float g_pre0[(size_t)T1 * B * G];      // layer-0 input gates, all steps
__device__ float g_c[NL][B * H];
__device__ float g_gates[NL][B * G];
__device__ __nv_bfloat16 g_hhi[NL][B * H];
__device__ __nv_bfloat16 g_hlo[NL][B * H];
__device__ __nv_bfloat16 g_wih_hi[NL * G * H];
__device__ __nv_bfloat16 g_wih_lo[NL * G * H];
__device__ __nv_bfloat16 g_whh_hi[NL * G * H];
__device__ __nv_bfloat16 g_whh_lo[NL * G * H];
__device__ __nv_bfloat16 g_xhi[(size_t)B * T1 * D];
__device__ __nv_bfloat16 g_xlo[(size_t)B * T1 * D];
__device__ unsigned g_bar_count;
__device__ unsigned g_gen;

// ---------------------------------------------------------------------------
// Software grid barrier (GRID=128 <= 148 SMs, 1 CTA/SM guaranteed co-resident)
// ---------------------------------------------------------------------------
__device__ __forceinline__ void grid_barrier() {
    __syncthreads();
    if (threadIdx.x == 0) {
        __threadfence();
        unsigned gen = *(volatile unsigned*)&g_gen;
        unsigned arrived = atomicAdd(&g_bar_count, 1u);
        if (arrived == GRID - 1) {
            g_bar_count = 0;
            __threadfence();
            *(volatile unsigned*)&g_gen = gen + 1;
        } else {
            while (*(volatile unsigned*)&g_gen == gen) {}
        }
        __threadfence();
    }
    __syncthreads();
}

__device__ __forceinline__ float sigm(float x) { return 1.f / (1.f + expf(-x)); }

// ---------------------------------------------------------------------------
// Tensor-core 64x64 tile GEMM (bf16 3-pass hi/lo split ~ fp32 accuracy):
//   acc += A[row0:row0+64, :512] * W[col0:col0+64, :512]^T
// A planes: [*, lda] bf16 hi/lo, k-contiguous. B planes: [2048, 512] bf16.
// 256 threads = 8 warps in 4x2; warp tile 16x32; mma.sync m16n8k16.
// acc[ntile][4] per lane; fragment mapping per PTX m16n8 C layout.
// ---------------------------------------------------------------------------
__device__ __forceinline__ void ldm4(uint32_t addr, uint32_t r[4]) {
    asm volatile("ldmatrix.sync.aligned.m8n8.x4.shared.b16 {%0,%1,%2,%3}, [%4];"
                 : "=r"(r[0]), "=r"(r[1]), "=r"(r[2]), "=r"(r[3]) : "r"(addr));
}
__device__ __forceinline__ void mma16816(float c[4], const uint32_t a[4],
                                         uint32_t b0, uint32_t b1) {
    asm volatile(
        "mma.sync.aligned.m16n8k16.row.col.f32.bf16.bf16.f32 "
        "{%0,%1,%2,%3},{%4,%5,%6,%7},{%8,%9},{%0,%1,%2,%3};"
        : "+f"(c[0]), "+f"(c[1]), "+f"(c[2]), "+f"(c[3])
        : "r"(a[0]), "r"(a[1]), "r"(a[2]), "r"(a[3]), "r"(b0), "r"(b1));
}

// smem: 4 planes x 64x64 bf16 (Ahi, Alo, Bhi, Blo), XOR-swizzled 16B segs
__device__ void mm_mma(const __nv_bfloat16* __restrict__ Ahi,
                       const __nv_bfloat16* __restrict__ Alo, int lda,
                       const __nv_bfloat16* __restrict__ Bhi,
                       const __nv_bfloat16* __restrict__ Blo,
                       int row0, int col0, float acc[4][4],
                       __nv_bfloat16* smem) {
    const int lane = threadIdx.x & 31, warp = threadIdx.x >> 5;
    const int wr = warp >> 1, wc = warp & 1;
    const int arow = wr * 16 + (lane & 15);
    const int ahalf = lane >> 4;              // k 8-seg select
    const int nrl = wc * 32 + ((lane >> 4) << 3) + (lane & 7);
    const int bhalf = (lane >> 3) & 1;
    uint32_t sbase = (uint32_t)__cvta_generic_to_shared(smem);

    for (int kc = 0; kc < 512; kc += 64) {
        // stage 64x64 of each plane into swizzled SMEM
        for (int s = threadIdx.x; s < 2048; s += NT) {
            int plane = s >> 9;
            int r = (s >> 3) & 63;
            int cs = s & 7;
            const __nv_bfloat16* src;
            if (plane == 0)      src = Ahi + (size_t)(row0 + r) * lda;
            else if (plane == 1) src = Alo + (size_t)(row0 + r) * lda;
            else if (plane == 2) src = Bhi + (size_t)(col0 + r) * 512;
            else                 src = Blo + (size_t)(col0 + r) * 512;
            uint4 v = *(const uint4*)(src + kc + cs * 8);
            *(uint4*)(smem + plane * 4096 + r * 64 + ((cs ^ (r & 7)) * 8)) = v;
        }
        __syncthreads();

#pragma unroll
        for (int sub = 0; sub < 4; sub++) {
            uint32_t ahi[4], alo[4];
            uint32_t aoff = (uint32_t)((arow * 64 + (((sub * 2 + ahalf) ^ (arow & 7)) * 8)) * 2);
            ldm4(sbase + 0 * 8192 + aoff, ahi);
            ldm4(sbase + 1 * 8192 + aoff, alo);
#pragma unroll
            for (int p = 0; p < 2; p++) {
                int nr = nrl + p * 16;
                uint32_t bhi[4], blo[4];
                uint32_t boff = (uint32_t)((nr * 64 + (((sub * 2 + bhalf) ^ (nr & 7)) * 8)) * 2);
                ldm4(sbase + 2 * 8192 + boff, bhi);
                ldm4(sbase + 3 * 8192 + boff, blo);
                // ntile p*2+0 uses regs {0,1}; p*2+1 uses {2,3}
                mma16816(acc[p * 2 + 0], ahi, bhi[0], bhi[1]);
                mma16816(acc[p * 2 + 0], ahi, blo[0], blo[1]);
                mma16816(acc[p * 2 + 0], alo, bhi[0], bhi[1]);
                mma16816(acc[p * 2 + 1], ahi, bhi[2], bhi[3]);
                mma16816(acc[p * 2 + 1], ahi, blo[2], blo[3]);
                mma16816(acc[p * 2 + 1], alo, bhi[2], bhi[3]);
            }
        }
        __syncthreads();
    }
}

// Per-lane output coordinates for acc[nt][e]
__device__ __forceinline__ void acc_coord(int nt, int e, int& r, int& c) {
    const int lane = threadIdx.x & 31, warp = threadIdx.x >> 5;
    const int wr = warp >> 1, wc = warp & 1;
    r = wr * 16 + (lane >> 2) + ((e >> 1) ? 8 : 0);
    c = wc * 32 + nt * 8 + (lane & 3) * 2 + (e & 1);
}

// ---------------------------------------------------------------------------
// Kernel 0: split weights into bf16 hi/lo planes
// ---------------------------------------------------------------------------
__global__ void split_w_kernel(const float* __restrict__ wih,
                               const float* __restrict__ whh) {
    int idx = blockIdx.x * blockDim.x + threadIdx.x;
    if (idx >= NL * G * H) return;
    float a = wih[idx];
    __nv_bfloat16 h1 = __float2bfloat16(a);
    g_wih_hi[idx] = h1;
    g_wih_lo[idx] = __float2bfloat16(a - __bfloat162float(h1));
    float b = whh[idx];
    __nv_bfloat16 h2 = __float2bfloat16(b);
    g_whh_hi[idx] = h2;
    g_whh_lo[idx] = __float2bfloat16(b - __bfloat162float(h2));
}

// ---------------------------------------------------------------------------
// Kernel 1: attention weights + input_weighted output (+ bf16 split planes).
// attn[b,d] = softmax_d( sum_t x[b,t,d]*attn_w[2H+t] )  (h/c terms drop out:
// constant across d, softmax shift-invariant) -- time-invariant.
// ---------------------------------------------------------------------------
__global__ void attn_kernel(const float* __restrict__ x, const float* __restrict__ aw,
                            float* __restrict__ out) {
    __shared__ float saw[T1];
    __shared__ float red[512];
    int b = blockIdx.x, d = threadIdx.x;
    if (d < T1) saw[d] = aw[2 * H + d];
    __syncthreads();
    const float* xb = x + (size_t)b * T1 * D;
    float acc = 0.f;
    for (int t = 0; t < T1; t++) acc += xb[(size_t)t * D + d] * saw[t];
    red[d] = acc;
    __syncthreads();
    for (int s = 256; s > 0; s >>= 1) {
        if (d < s) red[d] = fmaxf(red[d], red[d + s]);
        __syncthreads();
    }
    float mx = red[0];
    __syncthreads();
    float e = expf(acc - mx);
    red[d] = e;
    __syncthreads();
    for (int s = 256; s > 0; s >>= 1) {
        if (d < s) red[d] += red[d + s];
        __syncthreads();
    }
    float a = e / red[0];
    float* ob = out + (size_t)b * T1 * D;
    for (int t = 0; t < T1; t++) {
        float w = a * xb[(size_t)t * D + d];
        ob[(size_t)t * D + d] = w;
        __nv_bfloat16 hi = __float2bfloat16(w);
        size_t gi = (size_t)b * T1 * D + (size_t)t * D + d;
        g_xhi[gi] = hi;
        g_xlo[gi] = __float2bfloat16(w - __bfloat162float(hi));
    }
}

// ---------------------------------------------------------------------------
// Kernel 2: pre0[t][b][:] = weighted[b,t,:] @ W_ih[0]^T + b_ih0 + b_hh0
// grid = (T1*4, 32), 64x64 tiles, tensor-core path.
// ---------------------------------------------------------------------------
__global__ void __launch_bounds__(NT) pre_gemm_kernel(const float* __restrict__ bih,
                                                      const float* __restrict__ bhh) {
    __shared__ __align__(16) __nv_bfloat16 smem[4 * 4096];
    int tstep = blockIdx.x >> 2;
    int b0    = (blockIdx.x & 3) * 64;
    int col0  = blockIdx.y * 64;
    float acc[4][4] = {};
    mm_mma(g_xhi + (size_t)tstep * D, g_xlo + (size_t)tstep * D, T1 * D,
           g_wih_hi, g_wih_lo, b0, col0, acc, smem);
    size_t base = (size_t)tstep * B * G;
#pragma unroll
    for (int nt = 0; nt < 4; nt++)
#pragma unroll
        for (int e = 0; e < 4; e++) {
            int r, c;
            acc_coord(nt, e, r, c);
            int rr = b0 + r, cc = col0 + c;
            g_pre0[base + (size_t)rr * G + cc] = acc[nt][e] + bih[cc] + bhh[cc];
        }
}

// Elementwise LSTM cell update for layer l at step t (grid-strided)
__device__ __forceinline__ void lstm_ew(int l, int t, float* __restrict__ out) {
    for (int idx = blockIdx.x * NT + threadIdx.x; idx < B * H; idx += GRID * NT) {
        int b = idx >> 9;
        int k = idx & 511;
        const float* gb = &g_gates[l][(size_t)b * G];
        float ig = sigm(gb[k]);
        float fg = sigm(gb[H + k]);
        float gg = tanhf(gb[2 * H + k]);
        float og = sigm(gb[3 * H + k]);
        float c  = fg * g_c[l][idx] + ig * gg;
        float h  = og * tanhf(c);
        g_c[l][idx] = c;
        __nv_bfloat16 hh = __float2bfloat16(h);
        g_hhi[l][idx] = hh;
        g_hlo[l][idx] = __float2bfloat16(h - __bfloat162float(hh));
        if (l == NL - 1)
            out[OUT_ENC + (size_t)b * T1 * H + (size_t)t * H + k] = h;
    }
}

// ---------------------------------------------------------------------------
// Kernel 3: persistent recurrent kernel. 128 CTAs, software grid barriers.
// ---------------------------------------------------------------------------
__global__ void __launch_bounds__(NT, 1) lstm_kernel(const float* __restrict__ bih,
                                                     const float* __restrict__ bhh,
                                                     float* __restrict__ out) {
    __shared__ __align__(16) __nv_bfloat16 smem[4 * 4096];

    for (int idx = blockIdx.x * NT + threadIdx.x; idx < NL * B * H; idx += GRID * NT) {
        ((__nv_bfloat16*)g_hhi)[idx] = __float2bfloat16(0.f);
        ((__nv_bfloat16*)g_hlo)[idx] = __float2bfloat16(0.f);
        ((float*)g_c)[idx] = 0.f;
    }
    grid_barrier();

    const int tile = blockIdx.x;         // 0..127
    const int row0 = (tile >> 5) * 64;   // 4 row tiles over B=256
    const int col0 = (tile & 31) * 64;   // 32 col tiles over G=2048

    for (int t = 0; t < T1; t++) {
        // ---- phase 1: recurrent W_hh GEMMs for all 3 layers ----
        for (int l = 0; l < NL; l++) {
            float acc[4][4] = {};
            mm_mma(g_hhi[l], g_hlo[l], H,
                   g_whh_hi + (size_t)l * G * H, g_whh_lo + (size_t)l * G * H,
                   row0, col0, acc, smem);
            if (l == 0) {
                size_t pbase = (size_t)t * B * G;
#pragma unroll
                for (int nt = 0; nt < 4; nt++)
#pragma unroll
                    for (int e = 0; e < 4; e++) {
                        int r, c;
                        acc_coord(nt, e, r, c);
                        int rr = row0 + r, cc = col0 + c;
                        g_gates[0][(size_t)rr * G + cc] =
                            acc[nt][e] + g_pre0[pbase + (size_t)rr * G + cc];
                    }
            } else {
#pragma unroll
                for (int nt = 0; nt < 4; nt++)
#pragma unroll
                    for (int e = 0; e < 4; e++) {
                        int r, c;
                        acc_coord(nt, e, r, c);
                        int rr = row0 + r, cc = col0 + c;
                        g_gates[l][(size_t)rr * G + cc] =
                            acc[nt][e] + bih[l * G + cc] + bhh[l * G + cc];
                    }
            }
        }
        grid_barrier();

        lstm_ew(0, t, out);
        grid_barrier();

        // ---- gates1 += h0_new @ W_ih[1]^T ----
        {
            float acc[4][4] = {};
            mm_mma(g_hhi[0], g_hlo[0], H,
                   g_wih_hi + (size_t)1 * G * H, g_wih_lo + (size_t)1 * G * H,
                   row0, col0, acc, smem);
#pragma unroll
            for (int nt = 0; nt < 4; nt++)
#pragma unroll
                for (int e = 0; e < 4; e++) {
                    int r, c;
                    acc_coord(nt, e, r, c);
                    g_gates[1][(size_t)(row0 + r) * G + (col0 + c)] += acc[nt][e];
                }
        }
        grid_barrier();

        lstm_ew(1, t, out);
        grid_barrier();

        // ---- gates2 += h1_new @ W_ih[2]^T ----
        {
            float acc[4][4] = {};
            mm_mma(g_hhi[1], g_hlo[1], H,
                   g_wih_hi + (size_t)2 * G * H, g_wih_lo + (size_t)2 * G * H,
                   row0, col0, acc, smem);
#pragma unroll
            for (int nt = 0; nt < 4; nt++)
#pragma unroll
                for (int e = 0; e < 4; e++) {
                    int r, c;
                    acc_coord(nt, e, r, c);
                    g_gates[2][(size_t)(row0 + r) * G + (col0 + c)] += acc[nt][e];
                }
        }
        grid_barrier();

        lstm_ew(2, t, out);
        grid_barrier();
    }
}

// ---------------------------------------------------------------------------
extern "C" void kernel_launch(void* const* d_in, const int* in_sizes, int n_in,
                              void* d_out, int out_size) {
    const float* x   = (const float*)d_in[0];  // [B, T1, D]
    const float* wih = (const float*)d_in[1];  // [3, 2048, 512]
    const float* whh = (const float*)d_in[2];  // [3, 2048, 512]
    const float* bih = (const float*)d_in[3];  // [3, 2048]
    const float* bhh = (const float*)d_in[4];  // [3, 2048]
    const float* aw  = (const float*)d_in[5];  // [2H + T1, 1]
    float* out = (float*)d_out;                // [B*T1*D weighted | B*T1*H encoded]

    split_w_kernel<<<(NL * G * H + 255) / 256, 256>>>(wih, whh);
    attn_kernel<<<B, 512>>>(x, aw, out);
    dim3 pgrid(T1 * 4, G / 64);
    pre_gemm_kernel<<<pgrid, NT>>>(bih, bhh);
    lstm_kernel<<<GRID, NT>>>(bih, bhh, out);
}

// round 4
// speedup vs baseline: 2.8236x; 1.7264x over previous
#include <cuda_runtime.h>
#include <cuda_bf16.h>
#include <math.h>
#include <stdint.h>

// Problem constants
#define B   256
#define T1  127          // T-1 timesteps
#define D   512
#define H   512
#define G   2048         // 4*H gates
#define NL  3
#define OUT_ENC ((size_t)B * T1 * D)   // offset of input_encoded in d_out

// Persistent-kernel config
#define GRID 128
#define NT   256

// ---------------------------------------------------------------------------
// Scratch (device globals: allocation-free rule)
// ---------------------------------------------------------------------------
__device__ float g_pre0[(size_t)T1 * B * G];      // layer-0 input gates, all steps
__device__ float g_c[NL][B * H];
__device__ float g_gates[NL][B * G];
__device__ __nv_bfloat16 g_hhi[NL][B * H];
__device__ __nv_bfloat16 g_hlo[NL][B * H];
__device__ __nv_bfloat16 g_wih_hi[NL * G * H];
__device__ __nv_bfloat16 g_wih_lo[NL * G * H];
__device__ __nv_bfloat16 g_whh_hi[NL * G * H];
__device__ __nv_bfloat16 g_whh_lo[NL * G * H];
__device__ __nv_bfloat16 g_xhi[(size_t)B * T1 * D];
__device__ __nv_bfloat16 g_xlo[(size_t)B * T1 * D];
__device__ unsigned g_bar_count;
__device__ unsigned g_gen;

// ---------------------------------------------------------------------------
// Software grid barrier (GRID=128 <= 148 SMs, 1 CTA/SM guaranteed co-resident)
// ---------------------------------------------------------------------------
__device__ __forceinline__ void grid_barrier() {
    __syncthreads();
    if (threadIdx.x == 0) {
        __threadfence();
        unsigned gen = *(volatile unsigned*)&g_gen;
        unsigned arrived = atomicAdd(&g_bar_count, 1u);
        if (arrived == GRID - 1) {
            g_bar_count = 0;
            __threadfence();
            *(volatile unsigned*)&g_gen = gen + 1;
        } else {
            while (*(volatile unsigned*)&g_gen == gen) {}
        }
        __threadfence();
    }
    __syncthreads();
}

__device__ __forceinline__ float sigm(float x) { return 1.f / (1.f + expf(-x)); }

// ---------------------------------------------------------------------------
// cp.async helpers
// ---------------------------------------------------------------------------
__device__ __forceinline__ void cp16(__nv_bfloat16* dst, const __nv_bfloat16* src) {
    uint32_t d = (uint32_t)__cvta_generic_to_shared(dst);
    asm volatile("cp.async.cg.shared.global [%0], [%1], 16;" :: "r"(d), "l"(src));
}
#define CP_COMMIT() asm volatile("cp.async.commit_group;" ::: "memory")
#define CP_WAIT1()  asm volatile("cp.async.wait_group 1;" ::: "memory")

// ---------------------------------------------------------------------------
// Tensor-core 64x64 tile GEMM (bf16 3-pass hi/lo split ~ fp32 accuracy):
//   acc += A[row0:row0+64, :512] * W[col0:col0+64, :512]^T
// K chunked by 32, 3-stage cp.async ring, prefetch distance 2,
// ONE __syncthreads per chunk. SMEM: 3 stages x 4 planes x 64x32 bf16 = 48KB.
// Swizzle: seg' = seg ^ ((r>>1)&3) -> conflict-free LDSM (granule 4r+seg' mod 8
// injective over 8 consecutive rows).
// 256 threads = 8 warps 4x2; warp tile 16x32; mma.sync m16n8k16.
// ---------------------------------------------------------------------------
__device__ __forceinline__ void ldm4(uint32_t addr, uint32_t r[4]) {
    asm volatile("ldmatrix.sync.aligned.m8n8.x4.shared.b16 {%0,%1,%2,%3}, [%4];"
                 : "=r"(r[0]), "=r"(r[1]), "=r"(r[2]), "=r"(r[3]) : "r"(addr));
}
__device__ __forceinline__ void mma16816(float c[4], const uint32_t a[4],
                                         uint32_t b0, uint32_t b1) {
    asm volatile(
        "mma.sync.aligned.m16n8k16.row.col.f32.bf16.bf16.f32 "
        "{%0,%1,%2,%3},{%4,%5,%6,%7},{%8,%9},{%0,%1,%2,%3};"
        : "+f"(c[0]), "+f"(c[1]), "+f"(c[2]), "+f"(c[3])
        : "r"(a[0]), "r"(a[1]), "r"(a[2]), "r"(a[3]), "r"(b0), "r"(b1));
}

#define STG_ELEMS 8192   // elems per stage (4 planes * 64 * 32)

__device__ __forceinline__ void prefetch_chunk(
        const __nv_bfloat16* __restrict__ Ahi, const __nv_bfloat16* __restrict__ Alo,
        int lda,
        const __nv_bfloat16* __restrict__ Bhi, const __nv_bfloat16* __restrict__ Blo,
        int row0, int col0, int kc, __nv_bfloat16* stg) {
    const int r  = (threadIdx.x >> 2) & 63;
    const int cs = threadIdx.x & 3;
    const int koff = kc * 32 + cs * 8;
    __nv_bfloat16* d = stg + r * 32 + ((cs ^ ((r >> 1) & 3)) * 8);
    cp16(d + 0 * 2048, Ahi + (size_t)(row0 + r) * lda + koff);
    cp16(d + 1 * 2048, Alo + (size_t)(row0 + r) * lda + koff);
    cp16(d + 2 * 2048, Bhi + (size_t)(col0 + r) * 512 + koff);
    cp16(d + 3 * 2048, Blo + (size_t)(col0 + r) * 512 + koff);
}

__device__ void mm_mma(const __nv_bfloat16* __restrict__ Ahi,
                       const __nv_bfloat16* __restrict__ Alo, int lda,
                       const __nv_bfloat16* __restrict__ Bhi,
                       const __nv_bfloat16* __restrict__ Blo,
                       int row0, int col0, float acc[4][4],
                       __nv_bfloat16* smem) {
    const int lane = threadIdx.x & 31, warp = threadIdx.x >> 5;
    const int wr = warp >> 1, wc = warp & 1;
    const int arow  = wr * 16 + (lane & 15);
    const int ahalf = lane >> 4;
    const int nrl   = wc * 32 + ((lane >> 4) << 3) + (lane & 7);
    const int bhalf = (lane >> 3) & 1;
    const uint32_t sbase = (uint32_t)__cvta_generic_to_shared(smem);

    prefetch_chunk(Ahi, Alo, lda, Bhi, Blo, row0, col0, 0, smem);
    CP_COMMIT();
    prefetch_chunk(Ahi, Alo, lda, Bhi, Blo, row0, col0, 1, smem + STG_ELEMS);
    CP_COMMIT();

    for (int kc = 0; kc < 16; kc++) {
        CP_WAIT1();
        __syncthreads();
        if (kc + 2 < 16)
            prefetch_chunk(Ahi, Alo, lda, Bhi, Blo, row0, col0, kc + 2,
                           smem + ((kc + 2) % 3) * STG_ELEMS);
        CP_COMMIT();

        const uint32_t sb = sbase + (uint32_t)((kc % 3) * STG_ELEMS * 2);
#pragma unroll
        for (int sub = 0; sub < 2; sub++) {
            uint32_t ahi[4], alo[4];
            int aseg = (sub * 2 + ahalf) ^ ((arow >> 1) & 3);
            uint32_t aoff = (uint32_t)((arow * 32 + aseg * 8) * 2);
            ldm4(sb + 0 * 4096 + aoff, ahi);
            ldm4(sb + 1 * 4096 + aoff, alo);
#pragma unroll
            for (int p = 0; p < 2; p++) {
                int nr = nrl + p * 16;
                uint32_t bhi[4], blo[4];
                int bseg = (sub * 2 + bhalf) ^ ((nr >> 1) & 3);
                uint32_t boff = (uint32_t)((nr * 32 + bseg * 8) * 2);
                ldm4(sb + 2 * 4096 + boff, bhi);
                ldm4(sb + 3 * 4096 + boff, blo);
                mma16816(acc[p * 2 + 0], ahi, bhi[0], bhi[1]);
                mma16816(acc[p * 2 + 0], ahi, blo[0], blo[1]);
                mma16816(acc[p * 2 + 0], alo, bhi[0], bhi[1]);
                mma16816(acc[p * 2 + 1], ahi, bhi[2], bhi[3]);
                mma16816(acc[p * 2 + 1], ahi, blo[2], blo[3]);
                mma16816(acc[p * 2 + 1], alo, bhi[2], bhi[3]);
            }
        }
    }
    __syncthreads();   // protect stages before the next mm_mma's prefetch
}

// Per-lane output coordinates for acc[nt][e]
__device__ __forceinline__ void acc_coord(int nt, int e, int& r, int& c) {
    const int lane = threadIdx.x & 31, warp = threadIdx.x >> 5;
    const int wr = warp >> 1, wc = warp & 1;
    r = wr * 16 + (lane >> 2) + ((e >> 1) ? 8 : 0);
    c = wc * 32 + nt * 8 + (lane & 3) * 2 + (e & 1);
}

// ---------------------------------------------------------------------------
// Kernel 0: split weights into bf16 hi/lo planes
// ---------------------------------------------------------------------------
__global__ void split_w_kernel(const float* __restrict__ wih,
                               const float* __restrict__ whh) {
    int idx = blockIdx.x * blockDim.x + threadIdx.x;
    if (idx >= NL * G * H) return;
    float a = wih[idx];
    __nv_bfloat16 h1 = __float2bfloat16(a);
    g_wih_hi[idx] = h1;
    g_wih_lo[idx] = __float2bfloat16(a - __bfloat162float(h1));
    float b = whh[idx];
    __nv_bfloat16 h2 = __float2bfloat16(b);
    g_whh_hi[idx] = h2;
    g_whh_lo[idx] = __float2bfloat16(b - __bfloat162float(h2));
}

// ---------------------------------------------------------------------------
// Kernel 1: attention weights + input_weighted output (+ bf16 split planes).
// attn[b,d] = softmax_d( sum_t x[b,t,d]*attn_w[2H+t] )  (h/c terms drop out:
// constant across d, softmax shift-invariant) -- time-invariant.
// ---------------------------------------------------------------------------
__global__ void attn_kernel(const float* __restrict__ x, const float* __restrict__ aw,
                            float* __restrict__ out) {
    __shared__ float saw[T1];
    __shared__ float red[512];
    int b = blockIdx.x, d = threadIdx.x;
    if (d < T1) saw[d] = aw[2 * H + d];
    __syncthreads();
    const float* xb = x + (size_t)b * T1 * D;
    float acc = 0.f;
    for (int t = 0; t < T1; t++) acc += xb[(size_t)t * D + d] * saw[t];
    red[d] = acc;
    __syncthreads();
    for (int s = 256; s > 0; s >>= 1) {
        if (d < s) red[d] = fmaxf(red[d], red[d + s]);
        __syncthreads();
    }
    float mx = red[0];
    __syncthreads();
    float e = expf(acc - mx);
    red[d] = e;
    __syncthreads();
    for (int s = 256; s > 0; s >>= 1) {
        if (d < s) red[d] += red[d + s];
        __syncthreads();
    }
    float a = e / red[0];
    float* ob = out + (size_t)b * T1 * D;
    for (int t = 0; t < T1; t++) {
        float w = a * xb[(size_t)t * D + d];
        ob[(size_t)t * D + d] = w;
        __nv_bfloat16 hi = __float2bfloat16(w);
        size_t gi = (size_t)b * T1 * D + (size_t)t * D + d;
        g_xhi[gi] = hi;
        g_xlo[gi] = __float2bfloat16(w - __bfloat162float(hi));
    }
}

// ---------------------------------------------------------------------------
// Kernel 2: pre0[t][b][:] = weighted[b,t,:] @ W_ih[0]^T + b_ih0 + b_hh0
// grid = (T1*4, 32), 64x64 tiles, tensor-core path.
// ---------------------------------------------------------------------------
__global__ void __launch_bounds__(NT) pre_gemm_kernel(const float* __restrict__ bih,
                                                      const float* __restrict__ bhh) {
    __shared__ __align__(16) __nv_bfloat16 smem[3 * STG_ELEMS];
    int tstep = blockIdx.x >> 2;
    int b0    = (blockIdx.x & 3) * 64;
    int col0  = blockIdx.y * 64;
    float acc[4][4] = {};
    mm_mma(g_xhi + (size_t)tstep * D, g_xlo + (size_t)tstep * D, T1 * D,
           g_wih_hi, g_wih_lo, b0, col0, acc, smem);
    size_t base = (size_t)tstep * B * G;
#pragma unroll
    for (int nt = 0; nt < 4; nt++)
#pragma unroll
        for (int e = 0; e < 4; e++) {
            int r, c;
            acc_coord(nt, e, r, c);
            int rr = b0 + r, cc = col0 + c;
            g_pre0[base + (size_t)rr * G + cc] = acc[nt][e] + bih[cc] + bhh[cc];
        }
}

// Elementwise LSTM cell update for layer l at step t (grid-strided)
__device__ __forceinline__ void lstm_ew(int l, int t, float* __restrict__ out) {
    for (int idx = blockIdx.x * NT + threadIdx.x; idx < B * H; idx += GRID * NT) {
        int b = idx >> 9;
        int k = idx & 511;
        const float* gb = &g_gates[l][(size_t)b * G];
        float ig = sigm(gb[k]);
        float fg = sigm(gb[H + k]);
        float gg = tanhf(gb[2 * H + k]);
        float og = sigm(gb[3 * H + k]);
        float c  = fg * g_c[l][idx] + ig * gg;
        float h  = og * tanhf(c);
        g_c[l][idx] = c;
        __nv_bfloat16 hh = __float2bfloat16(h);
        g_hhi[l][idx] = hh;
        g_hlo[l][idx] = __float2bfloat16(h - __bfloat162float(hh));
        if (l == NL - 1)
            out[OUT_ENC + (size_t)b * T1 * H + (size_t)t * H + k] = h;
    }
}

// ---------------------------------------------------------------------------
// Kernel 3: persistent recurrent kernel. 128 CTAs, software grid barriers.
// ---------------------------------------------------------------------------
__global__ void __launch_bounds__(NT, 1) lstm_kernel(const float* __restrict__ bih,
                                                     const float* __restrict__ bhh,
                                                     float* __restrict__ out) {
    __shared__ __align__(16) __nv_bfloat16 smem[3 * STG_ELEMS];

    for (int idx = blockIdx.x * NT + threadIdx.x; idx < NL * B * H; idx += GRID * NT) {
        ((__nv_bfloat16*)g_hhi)[idx] = __float2bfloat16(0.f);
        ((__nv_bfloat16*)g_hlo)[idx] = __float2bfloat16(0.f);
        ((float*)g_c)[idx] = 0.f;
    }
    grid_barrier();

    const int tile = blockIdx.x;         // 0..127
    const int row0 = (tile >> 5) * 64;   // 4 row tiles over B=256
    const int col0 = (tile & 31) * 64;   // 32 col tiles over G=2048

    for (int t = 0; t < T1; t++) {
        // ---- phase 1: recurrent W_hh GEMMs for all 3 layers ----
        for (int l = 0; l < NL; l++) {
            float acc[4][4] = {};
            mm_mma(g_hhi[l], g_hlo[l], H,
                   g_whh_hi + (size_t)l * G * H, g_whh_lo + (size_t)l * G * H,
                   row0, col0, acc, smem);
            if (l == 0) {
                size_t pbase = (size_t)t * B * G;
#pragma unroll
                for (int nt = 0; nt < 4; nt++)
#pragma unroll
                    for (int e = 0; e < 4; e++) {
                        int r, c;
                        acc_coord(nt, e, r, c);
                        int rr = row0 + r, cc = col0 + c;
                        g_gates[0][(size_t)rr * G + cc] =
                            acc[nt][e] + g_pre0[pbase + (size_t)rr * G + cc];
                    }
            } else {
#pragma unroll
                for (int nt = 0; nt < 4; nt++)
#pragma unroll
                    for (int e = 0; e < 4; e++) {
                        int r, c;
                        acc_coord(nt, e, r, c);
                        int rr = row0 + r, cc = col0 + c;
                        g_gates[l][(size_t)rr * G + cc] =
                            acc[nt][e] + bih[l * G + cc] + bhh[l * G + cc];
                    }
            }
        }
        grid_barrier();

        lstm_ew(0, t, out);
        grid_barrier();

        // ---- gates1 += h0_new @ W_ih[1]^T ----
        {
            float acc[4][4] = {};
            mm_mma(g_hhi[0], g_hlo[0], H,
                   g_wih_hi + (size_t)1 * G * H, g_wih_lo + (size_t)1 * G * H,
                   row0, col0, acc, smem);
#pragma unroll
            for (int nt = 0; nt < 4; nt++)
#pragma unroll
                for (int e = 0; e < 4; e++) {
                    int r, c;
                    acc_coord(nt, e, r, c);
                    g_gates[1][(size_t)(row0 + r) * G + (col0 + c)] += acc[nt][e];
                }
        }
        grid_barrier();

        lstm_ew(1, t, out);
        grid_barrier();

        // ---- gates2 += h1_new @ W_ih[2]^T ----
        {
            float acc[4][4] = {};
            mm_mma(g_hhi[1], g_hlo[1], H,
                   g_wih_hi + (size_t)2 * G * H, g_wih_lo + (size_t)2 * G * H,
                   row0, col0, acc, smem);
#pragma unroll
            for (int nt = 0; nt < 4; nt++)
#pragma unroll
                for (int e = 0; e < 4; e++) {
                    int r, c;
                    acc_coord(nt, e, r, c);
                    g_gates[2][(size_t)(row0 + r) * G + (col0 + c)] += acc[nt][e];
                }
        }
        grid_barrier();

        lstm_ew(2, t, out);
        grid_barrier();
    }
}

// ---------------------------------------------------------------------------
extern "C" void kernel_launch(void* const* d_in, const int* in_sizes, int n_in,
                              void* d_out, int out_size) {
    const float* x   = (const float*)d_in[0];  // [B, T1, D]
    const float* wih = (const float*)d_in[1];  // [3, 2048, 512]
    const float* whh = (const float*)d_in[2];  // [3, 2048, 512]
    const float* bih = (const float*)d_in[3];  // [3, 2048]
    const float* bhh = (const float*)d_in[4];  // [3, 2048]
    const float* aw  = (const float*)d_in[5];  // [2H + T1, 1]
    float* out = (float*)d_out;                // [B*T1*D weighted | B*T1*H encoded]

    split_w_kernel<<<(NL * G * H + 255) / 256, 256>>>(wih, whh);
    attn_kernel<<<B, 512>>>(x, aw, out);
    dim3 pgrid(T1 * 4, G / 64);
    pre_gemm_kernel<<<pgrid, NT>>>(bih, bhh);
    lstm_kernel<<<GRID, NT>>>(bih, bhh, out);
}

// round 5
// speedup vs baseline: 3.4067x; 1.2065x over previous
#include <cuda_runtime.h>
#include <cuda_bf16.h>
#include <math.h>
#include <stdint.h>

// Problem constants
#define B   256
#define T1  127
#define D   512
#define H   512
#define G   2048
#define NL  3
#define OUT_ENC ((size_t)B * T1 * D)

#define GRID 128
#define NT   256

typedef __nv_bfloat16 bf;

// ---------------------------------------------------------------------------
// Scratch
// ---------------------------------------------------------------------------
__device__ float g_pre0[(size_t)T1 * B * G];   // remapped: [t][b][tilec*64 + (q*16+j)]
__device__ bf g_hhi[2][NL][B * H];             // step-parity double buffer
__device__ bf g_hlo[2][NL][B * H];
__device__ bf g_wih_hi[NL * G * H];
__device__ bf g_wih_lo[NL * G * H];
__device__ bf g_whh_hi[NL * G * H];
__device__ bf g_whh_lo[NL * G * H];
__device__ bf g_xhi[(size_t)B * T1 * D];
__device__ bf g_xlo[(size_t)B * T1 * D];
__device__ unsigned g_bar_count;
__device__ unsigned g_gen;

// ---------------------------------------------------------------------------
__device__ __forceinline__ void grid_barrier() {
    __syncthreads();
    if (threadIdx.x == 0) {
        __threadfence();
        unsigned gen = *(volatile unsigned*)&g_gen;
        unsigned arrived = atomicAdd(&g_bar_count, 1u);
        if (arrived == GRID - 1) {
            g_bar_count = 0;
            __threadfence();
            *(volatile unsigned*)&g_gen = gen + 1;
        } else {
            while (*(volatile unsigned*)&g_gen == gen) {}
        }
        __threadfence();
    }
    __syncthreads();
}

__device__ __forceinline__ float sigm(float x) { return 1.f / (1.f + expf(-x)); }

// ---------------------------------------------------------------------------
__device__ __forceinline__ void cp16(bf* dst, const bf* src) {
    uint32_t d = (uint32_t)__cvta_generic_to_shared(dst);
    asm volatile("cp.async.cg.shared.global [%0], [%1], 16;" :: "r"(d), "l"(src));
}
#define CP_COMMIT() asm volatile("cp.async.commit_group;" ::: "memory")
#define CP_WAIT1()  asm volatile("cp.async.wait_group 1;" ::: "memory")

__device__ __forceinline__ void ldm4(uint32_t addr, uint32_t r[4]) {
    asm volatile("ldmatrix.sync.aligned.m8n8.x4.shared.b16 {%0,%1,%2,%3}, [%4];"
                 : "=r"(r[0]), "=r"(r[1]), "=r"(r[2]), "=r"(r[3]) : "r"(addr));
}
__device__ __forceinline__ void mma16816(float c[4], const uint32_t a[4],
                                         uint32_t b0, uint32_t b1) {
    asm volatile(
        "mma.sync.aligned.m16n8k16.row.col.f32.bf16.bf16.f32 "
        "{%0,%1,%2,%3},{%4,%5,%6,%7},{%8,%9},{%0,%1,%2,%3};"
        : "+f"(c[0]), "+f"(c[1]), "+f"(c[2]), "+f"(c[3])
        : "r"(a[0]), "r"(a[1]), "r"(a[2]), "r"(a[3]), "r"(b0), "r"(b1));
}

#define STG_ELEMS 8192   // 4 planes * 64 * 32 bf16 per stage

// W gather: SMEM row r -> W row (r>>4)*512 + colbase + (r&15)  (gate quadrants)
// A: rows row0+r with leading dim lda_a (bf16 elems).
// Fused K: chunks [0,16) from A1/W1; [16,nch) from A2/W2.
__device__ __forceinline__ void prefetch_chunk(
        const bf* __restrict__ A1hi, const bf* __restrict__ A1lo, int lda_a,
        const bf* __restrict__ W1hi, const bf* __restrict__ W1lo,
        const bf* __restrict__ A2hi, const bf* __restrict__ A2lo,
        const bf* __restrict__ W2hi, const bf* __restrict__ W2lo,
        int row0, int colbase, int kc, bf* stg) {
    const int r  = (threadIdx.x >> 2) & 63;
    const int cs = threadIdx.x & 3;
    const int wrow = ((r >> 4) << 9) + colbase + (r & 15);
    const bf *ahi, *alo, *whi, *wlo;
    int koff;
    if (kc < 16) {
        koff = kc * 32 + cs * 8;
        ahi = A1hi; alo = A1lo; whi = W1hi; wlo = W1lo;
    } else {
        koff = (kc - 16) * 32 + cs * 8;
        ahi = A2hi; alo = A2lo; whi = W2hi; wlo = W2lo;
    }
    bf* d = stg + r * 32 + ((cs ^ ((r >> 1) & 3)) * 8);
    cp16(d + 0 * 2048, ahi + (size_t)(row0 + r) * lda_a + koff);
    cp16(d + 1 * 2048, alo + (size_t)(row0 + r) * lda_a + koff);
    cp16(d + 2 * 2048, whi + (size_t)wrow * 512 + koff);
    cp16(d + 3 * 2048, wlo + (size_t)wrow * 512 + koff);
}

// 64x64 tile, bf16 3-pass split, 3-stage cp.async ring, acc interleaved.
__device__ void mm_tile(const bf* A1hi, const bf* A1lo, int lda_a,
                        const bf* W1hi, const bf* W1lo,
                        const bf* A2hi, const bf* A2lo,
                        const bf* W2hi, const bf* W2lo,
                        int row0, int colbase, int nch,
                        float acc[4][4], bf* smem) {
    const int lane = threadIdx.x & 31;
    const int warp = threadIdx.x >> 5;
    const int wr = warp >> 1, wc = warp & 1;
    const int arow  = wr * 16 + (lane & 15);
    const int ahalf = lane >> 4;
    const int nrl   = wc * 32 + ((lane >> 4) << 3) + (lane & 7);
    const int bhalf = (lane >> 3) & 1;
    const uint32_t sbase = (uint32_t)__cvta_generic_to_shared(smem);

    prefetch_chunk(A1hi,A1lo,lda_a,W1hi,W1lo,A2hi,A2lo,W2hi,W2lo,row0,colbase,0,smem);
    CP_COMMIT();
    prefetch_chunk(A1hi,A1lo,lda_a,W1hi,W1lo,A2hi,A2lo,W2hi,W2lo,row0,colbase,1,smem+STG_ELEMS);
    CP_COMMIT();

    for (int kc = 0; kc < nch; kc++) {
        CP_WAIT1();
        __syncthreads();
        if (kc + 2 < nch)
            prefetch_chunk(A1hi,A1lo,lda_a,W1hi,W1lo,A2hi,A2lo,W2hi,W2lo,
                           row0,colbase,kc+2, smem + ((kc+2)%3)*STG_ELEMS);
        CP_COMMIT();

        const uint32_t sb = sbase + (uint32_t)((kc % 3) * STG_ELEMS * 2);
#pragma unroll
        for (int sub = 0; sub < 2; sub++) {
            uint32_t ahi[4], alo[4];
            int aseg = (sub * 2 + ahalf) ^ ((arow >> 1) & 3);
            uint32_t aoff = (uint32_t)((arow * 32 + aseg * 8) * 2);
            ldm4(sb + 0 * 4096 + aoff, ahi);
            ldm4(sb + 1 * 4096 + aoff, alo);
            uint32_t bh0[4], bl0[4], bh1[4], bl1[4];
            {
                int nr = nrl;
                int bseg = (sub * 2 + bhalf) ^ ((nr >> 1) & 3);
                uint32_t boff = (uint32_t)((nr * 32 + bseg * 8) * 2);
                ldm4(sb + 2 * 4096 + boff, bh0);
                ldm4(sb + 3 * 4096 + boff, bl0);
            }
            {
                int nr = nrl + 16;
                int bseg = (sub * 2 + bhalf) ^ ((nr >> 1) & 3);
                uint32_t boff = (uint32_t)((nr * 32 + bseg * 8) * 2);
                ldm4(sb + 2 * 4096 + boff, bh1);
                ldm4(sb + 3 * 4096 + boff, bl1);
            }
            // round-robin across 4 accumulators (dep distance 4)
            mma16816(acc[0], ahi, bh0[0], bh0[1]);
            mma16816(acc[1], ahi, bh0[2], bh0[3]);
            mma16816(acc[2], ahi, bh1[0], bh1[1]);
            mma16816(acc[3], ahi, bh1[2], bh1[3]);
            mma16816(acc[0], ahi, bl0[0], bl0[1]);
            mma16816(acc[1], ahi, bl0[2], bl0[3]);
            mma16816(acc[2], ahi, bl1[0], bl1[1]);
            mma16816(acc[3], ahi, bl1[2], bl1[3]);
            mma16816(acc[0], alo, bh0[0], bh0[1]);
            mma16816(acc[1], alo, bh0[2], bh0[3]);
            mma16816(acc[2], alo, bh1[0], bh1[1]);
            mma16816(acc[3], alo, bh1[2], bh1[3]);
        }
    }
    __syncthreads();
}

__device__ __forceinline__ void acc_coord(int nt, int e, int& r, int& c) {
    const int lane = threadIdx.x & 31, warp = threadIdx.x >> 5;
    const int wr = warp >> 1, wc = warp & 1;
    r = wr * 16 + (lane >> 2) + ((e >> 1) ? 8 : 0);
    c = wc * 32 + nt * 8 + (lane & 3) * 2 + (e & 1);
}

// ---------------------------------------------------------------------------
__global__ void split_w_kernel(const float* __restrict__ wih,
                               const float* __restrict__ whh) {
    int idx = blockIdx.x * blockDim.x + threadIdx.x;
    if (idx >= NL * G * H) return;
    float a = wih[idx];
    bf h1 = __float2bfloat16(a);
    g_wih_hi[idx] = h1;
    g_wih_lo[idx] = __float2bfloat16(a - __bfloat162float(h1));
    float b = whh[idx];
    bf h2 = __float2bfloat16(b);
    g_whh_hi[idx] = h2;
    g_whh_lo[idx] = __float2bfloat16(b - __bfloat162float(h2));
}

// ---------------------------------------------------------------------------
// attn[b,d] = softmax_d( sum_t x[b,t,d]*attn_w[2H+t] )  — time-invariant.
// ---------------------------------------------------------------------------
__global__ void attn_kernel(const float* __restrict__ x, const float* __restrict__ aw,
                            float* __restrict__ out) {
    __shared__ float saw[T1];
    __shared__ float red[512];
    int b = blockIdx.x, d = threadIdx.x;
    if (d < T1) saw[d] = aw[2 * H + d];
    __syncthreads();
    const float* xb = x + (size_t)b * T1 * D;
    float acc = 0.f;
    for (int t = 0; t < T1; t++) acc += xb[(size_t)t * D + d] * saw[t];
    red[d] = acc;
    __syncthreads();
    for (int s = 256; s > 0; s >>= 1) {
        if (d < s) red[d] = fmaxf(red[d], red[d + s]);
        __syncthreads();
    }
    float mx = red[0];
    __syncthreads();
    float e = expf(acc - mx);
    red[d] = e;
    __syncthreads();
    for (int s = 256; s > 0; s >>= 1) {
        if (d < s) red[d] += red[d + s];
        __syncthreads();
    }
    float a = e / red[0];
    float* ob = out + (size_t)b * T1 * D;
    for (int t = 0; t < T1; t++) {
        float w = a * xb[(size_t)t * D + d];
        ob[(size_t)t * D + d] = w;
        bf hi = __float2bfloat16(w);
        size_t gi = (size_t)b * T1 * D + (size_t)t * D + d;
        g_xhi[gi] = hi;
        g_xlo[gi] = __float2bfloat16(w - __bfloat162float(hi));
    }
}

// ---------------------------------------------------------------------------
// pre0 (remapped layout): pre0[t][b][tilec*64 + c] = weighted@Wih0^T + biases
// with c -> W row (c>>4)*512 + tilec*16 + (c&15)
// ---------------------------------------------------------------------------
__global__ void __launch_bounds__(NT) pre_gemm_kernel(const float* __restrict__ bih,
                                                      const float* __restrict__ bhh) {
    __shared__ __align__(16) bf smem[3 * STG_ELEMS];
    int tstep = blockIdx.x >> 2;
    int b0    = (blockIdx.x & 3) * 64;
    int tilec = blockIdx.y;
    int colbase = tilec * 16;
    float acc[4][4] = {};
    mm_tile(g_xhi + (size_t)tstep * D, g_xlo + (size_t)tstep * D, T1 * D,
            g_wih_hi, g_wih_lo, 0, 0, 0, 0, b0, colbase, 16, acc, smem);
    size_t base = (size_t)tstep * B * G;
#pragma unroll
    for (int nt = 0; nt < 4; nt++)
#pragma unroll
        for (int e = 0; e < 4; e++) {
            int r, c;
            acc_coord(nt, e, r, c);
            int bcol = ((c >> 4) << 9) + colbase + (c & 15);
            g_pre0[base + (size_t)(b0 + r) * G + tilec * 64 + c] =
                acc[nt][e] + bih[bcol] + bhh[bcol];
        }
}

// ---------------------------------------------------------------------------
// Persistent recurrent kernel: 128 CTAs, 3 grid barriers per step.
// CTA tile: batch rows row0..+63, gate cols q*512+colbase+j (q=0..3, j=0..15).
// Cell state c lives in CTA SMEM across all steps. h double-buffered by parity.
// ---------------------------------------------------------------------------
__global__ void __launch_bounds__(NT, 1) lstm_kernel(const float* __restrict__ bih,
                                                     const float* __restrict__ bhh,
                                                     float* __restrict__ out) {
    __shared__ __align__(16) bf smem[3 * STG_ELEMS];        // 48KB ring
    __shared__ float sg[64][65];                             // gate tile
    __shared__ float sc[NL][64 * 16];                        // cell state
    __shared__ float sbias[2][64];                           // layer 1,2 biases

    const int tile = blockIdx.x;
    const int row0    = (tile >> 5) * 64;
    const int tilec   = tile & 31;
    const int colbase = tilec * 16;
    const int tid = threadIdx.x;

    // init: zero h parity 1 (the "prev" buffer at t=0), cell state, biases
    for (int idx = blockIdx.x * NT + tid; idx < NL * B * H; idx += GRID * NT) {
        ((bf*)g_hhi[1])[idx] = __float2bfloat16(0.f);
        ((bf*)g_hlo[1])[idx] = __float2bfloat16(0.f);
    }
    for (int k = tid; k < NL * 64 * 16; k += NT) ((float*)sc)[k] = 0.f;
    if (tid < 128) {
        int l = (tid >> 6) + 1, c = tid & 63;
        int bcol = l * G + ((c >> 4) << 9) + colbase + (c & 15);
        sbias[l - 1][c] = bih[bcol] + bhh[bcol];
    }
    grid_barrier();

    for (int t = 0; t < T1; t++) {
        const int np = t & 1, op = np ^ 1;
        for (int l = 0; l < NL; l++) {
            float acc[4][4] = {};
            if (l == 0) {
                mm_tile(g_hhi[op][0], g_hlo[op][0], 512,
                        g_whh_hi, g_whh_lo, 0, 0, 0, 0,
                        row0, colbase, 16, acc, smem);
            } else {
                mm_tile(g_hhi[op][l], g_hlo[op][l], 512,
                        g_whh_hi + (size_t)l * G * H, g_whh_lo + (size_t)l * G * H,
                        g_hhi[np][l - 1], g_hlo[np][l - 1],
                        g_wih_hi + (size_t)l * G * H, g_wih_lo + (size_t)l * G * H,
                        row0, colbase, 32, acc, smem);
            }
            // stash gate tile in SMEM
#pragma unroll
            for (int nt = 0; nt < 4; nt++)
#pragma unroll
                for (int e = 0; e < 4; e++) {
                    int r, c;
                    acc_coord(nt, e, r, c);
                    sg[r][c] = acc[nt][e];
                }
            __syncthreads();

            // CTA-local cell update (1024 cells, 4 per thread)
#pragma unroll
            for (int k = 0; k < 4; k++) {
                int idx = tid + k * NT;
                int b = idx >> 4, j = idx & 15;
                float gi = sg[b][j], gf = sg[b][16 + j],
                      gg = sg[b][32 + j], go = sg[b][48 + j];
                if (l == 0) {
                    const float* p = g_pre0 + (size_t)t * B * G
                                   + (size_t)(row0 + b) * G + tilec * 64;
                    gi += p[j]; gf += p[16 + j]; gg += p[32 + j]; go += p[48 + j];
                } else {
                    const float* sb2 = sbias[l - 1];
                    gi += sb2[j]; gf += sb2[16 + j]; gg += sb2[32 + j]; go += sb2[48 + j];
                }
                float i_ = sigm(gi), f_ = sigm(gf), g_ = tanhf(gg), o_ = sigm(go);
                float cn = f_ * sc[l][idx] + i_ * g_;
                float hn = o_ * tanhf(cn);
                sc[l][idx] = cn;
                bf hh = __float2bfloat16(hn);
                size_t hidx = (size_t)(row0 + b) * H + colbase + j;
                g_hhi[np][l][hidx] = hh;
                g_hlo[np][l][hidx] = __float2bfloat16(hn - __bfloat162float(hh));
                if (l == NL - 1)
                    out[OUT_ENC + (size_t)(row0 + b) * T1 * H + (size_t)t * H
                        + colbase + j] = hn;
            }
            grid_barrier();
        }
    }
}

// ---------------------------------------------------------------------------
extern "C" void kernel_launch(void* const* d_in, const int* in_sizes, int n_in,
                              void* d_out, int out_size) {
    const float* x   = (const float*)d_in[0];
    const float* wih = (const float*)d_in[1];
    const float* whh = (const float*)d_in[2];
    const float* bih = (const float*)d_in[3];
    const float* bhh = (const float*)d_in[4];
    const float* aw  = (const float*)d_in[5];
    float* out = (float*)d_out;

    split_w_kernel<<<(NL * G * H + 255) / 256, 256>>>(wih, whh);
    attn_kernel<<<B, 512>>>(x, aw, out);
    dim3 pgrid(T1 * 4, G / 64);
    pre_gemm_kernel<<<pgrid, NT>>>(bih, bhh);
    lstm_kernel<<<GRID, NT>>>(bih, bhh, out);
}